// round 8
// baseline (speedup 1.0000x reference)
#include <cuda_runtime.h>
#include <cstdint>

// Gate pipeline (3 kernels):
//   K1: conv 4x4/s4 [64,3,512,512] -> gate[64,128,128]
//   K2: per-batch exact K-th-largest key (radix select, low-barrier)
//   K3: out = in * (gate >= thr ? gate : 0), 4x upsample, 3ch bcast.
//       One thread = 2 gate cells x 4 rows: MLP=8, sector-exact read skip.
__device__ float    d_gate[64 * 16384];
__device__ unsigned d_thr[64];

__device__ __forceinline__ unsigned f2key(float f) {
    unsigned u = __float_as_uint(f);
    return (u & 0x80000000u) ? ~u : (u | 0x80000000u);  // monotone float->uint
}

// ---------------------------------------------------------------------------
// Kernel 1: conv. One thread per gate pixel, 12 coalesced float4 loads.
// Measured 79-80% DRAM — at the read-stream ceiling.
// ---------------------------------------------------------------------------
__global__ void gate_conv_kernel(const float4* __restrict__ in,
                                 const float* __restrict__ wk) {
    __shared__ float4 w[12];
    int t = threadIdx.x;
    if (t < 12) w[t] = reinterpret_cast<const float4*>(wk)[t];
    __syncthreads();

    int idx = blockIdx.x * blockDim.x + t;      // [0, 64*16384)
    int x = idx & 127;
    int y = (idx >> 7) & 127;
    int b = idx >> 14;

    const float4* base = in + (size_t)b * 196608 + x;
    float sum = 0.0f;
#pragma unroll
    for (int c = 0; c < 3; c++) {
#pragma unroll
        for (int i = 0; i < 4; i++) {
            float4 v = base[c * 65536 + (4 * y + i) * 128];
            float4 ww = w[c * 4 + i];
            sum += v.x * ww.x + v.y * ww.y + v.z * ww.z + v.w * ww.w;
        }
    }
    d_gate[idx] = sum;
}

// ---------------------------------------------------------------------------
// Kernel 2: per-batch K-th-largest key, MSB-first radix select, 4x8-bit.
// Register-resident keys (float4 loads); warp-private histograms (match_any
// leader updates, no atomics); single-warp shfl suffix scan -> 4 barriers
// per pass. One block per batch, 512 threads.
// ---------------------------------------------------------------------------
__global__ void __launch_bounds__(512) gate_select_kernel() {
    __shared__ unsigned hist[16][256];   // per-warp private
    __shared__ int cnt[256];
    __shared__ unsigned s_prefix;
    __shared__ int s_k;

    const int row = blockIdx.x;
    const int t = threadIdx.x;          // blockDim = 512
    const int warp = t >> 5;
    const int lane = t & 31;

    // vectorized one-shot key load: 8 float4 = 32 keys per thread
    unsigned key[32];
    const float4* g4 = reinterpret_cast<const float4*>(d_gate + row * 16384);
#pragma unroll
    for (int i = 0; i < 8; i++) {
        float4 v = g4[t + i * 512];
        key[4 * i + 0] = f2key(v.x);
        key[4 * i + 1] = f2key(v.y);
        key[4 * i + 2] = f2key(v.z);
        key[4 * i + 3] = f2key(v.w);
    }

    if (t == 0) { s_prefix = 0u; s_k = 4096; }

#pragma unroll
    for (int pass = 0; pass < 4; pass++) {
        const int shift = 24 - 8 * pass;
        for (int i = t; i < 16 * 256; i += 512)
            (&hist[0][0])[i] = 0u;
        __syncthreads();                               // barrier 1

        const unsigned pmask = pass ? (0xFFFFFFFFu << (32 - 8 * pass)) : 0u;
        const unsigned prefix = s_prefix;
        const int kcur = s_k;

#pragma unroll
        for (int i = 0; i < 32; i++) {
            unsigned u = key[i];
            unsigned bin = ((u & pmask) == prefix) ? ((u >> shift) & 0xFFu)
                                                   : 0xFFFFFFFFu;
            unsigned same = __match_any_sync(0xFFFFFFFFu, bin);
            if (bin != 0xFFFFFFFFu && lane == (__ffs(same) - 1))
                hist[warp][bin] += __popc(same);       // warp-private
        }
        __syncthreads();                               // barrier 2

        if (t < 256) {
            int c = 0;
#pragma unroll
            for (int wg = 0; wg < 16; wg++) c += hist[wg][t];
            cnt[t] = c;
        }
        __syncthreads();                               // barrier 3

        // warp 0: suffix scan over 256 bins (8 bins per lane) + pick bin
        if (warp == 0) {
            int v[8], s[8];
#pragma unroll
            for (int j = 0; j < 8; j++) v[j] = cnt[lane * 8 + j];
            s[7] = v[7];
#pragma unroll
            for (int j = 6; j >= 0; j--) s[j] = s[j + 1] + v[j];
            int suf = s[0];
#pragma unroll
            for (int off = 1; off < 32; off <<= 1) {
                int o = __shfl_down_sync(0xFFFFFFFFu, suf, off);
                if (lane + off < 32) suf += o;
            }
            int above_lanes = suf - s[0];   // sum over lanes > lane
#pragma unroll
            for (int j = 0; j < 8; j++) {
                int Sj = s[j] + above_lanes;
                int Sn = (j < 7 ? s[j + 1] : 0) + above_lanes;
                if (Sj >= kcur && Sn < kcur) {   // exactly one (lane,j) hits
                    s_prefix = prefix | ((unsigned)(lane * 8 + j) << shift);
                    s_k = kcur - Sn;
                }
            }
        }
        __syncthreads();                               // barrier 4
    }

    if (t == 0) d_thr[row] = s_prefix;   // exact key of K-th largest
}

// ---------------------------------------------------------------------------
// Kernel 3: out = in * gate. One thread = 2 vertically-adjacent gate cells
// x 4 image rows each = 8 rows: up to 8 INDEPENDENT in loads (MLP=8),
// 8 streaming stores. Warp per-instruction access = contiguous 512B.
// ---------------------------------------------------------------------------
__global__ void gate_mul_kernel(const float4* __restrict__ in,
                                float4* __restrict__ out) {
    int i   = blockIdx.x * blockDim.x + threadIdx.x;  // [0, 128*64)
    int x4  = i & 127;             // float4 col == gate col
    int gy2 = i >> 7;              // gate row pair (0..63)
    int c   = blockIdx.y;          // channel
    int b   = blockIdx.z;          // batch

    unsigned thr = __ldg(&d_thr[b]);
    const float* gp = &d_gate[b * 16384 + (2 * gy2) * 128 + x4];
    float gv0 = __ldg(gp);
    float gv1 = __ldg(gp + 128);
    bool a0 = f2key(gv0) >= thr;
    bool a1 = f2key(gv1) >= thr;

    size_t base = (size_t)(b * 3 + c) * 65536 + (size_t)(8 * gy2) * 128 + x4;

    float4 z = make_float4(0.f, 0.f, 0.f, 0.f);
    float4 v[8];
#pragma unroll
    for (int r = 0; r < 8; r++) v[r] = z;

    if (a0) {
        float4 t0 = in[base];
        float4 t1 = in[base + 128];
        float4 t2 = in[base + 256];
        float4 t3 = in[base + 384];
        v[0].x = t0.x * gv0; v[0].y = t0.y * gv0; v[0].z = t0.z * gv0; v[0].w = t0.w * gv0;
        v[1].x = t1.x * gv0; v[1].y = t1.y * gv0; v[1].z = t1.z * gv0; v[1].w = t1.w * gv0;
        v[2].x = t2.x * gv0; v[2].y = t2.y * gv0; v[2].z = t2.z * gv0; v[2].w = t2.w * gv0;
        v[3].x = t3.x * gv0; v[3].y = t3.y * gv0; v[3].z = t3.z * gv0; v[3].w = t3.w * gv0;
    }
    if (a1) {
        float4 t4 = in[base + 512];
        float4 t5 = in[base + 640];
        float4 t6 = in[base + 768];
        float4 t7 = in[base + 896];
        v[4].x = t4.x * gv1; v[4].y = t4.y * gv1; v[4].z = t4.z * gv1; v[4].w = t4.w * gv1;
        v[5].x = t5.x * gv1; v[5].y = t5.y * gv1; v[5].z = t5.z * gv1; v[5].w = t5.w * gv1;
        v[6].x = t6.x * gv1; v[6].y = t6.y * gv1; v[6].z = t6.z * gv1; v[6].w = t6.w * gv1;
        v[7].x = t7.x * gv1; v[7].y = t7.y * gv1; v[7].z = t7.z * gv1; v[7].w = t7.w * gv1;
    }
#pragma unroll
    for (int r = 0; r < 8; r++)
        __stcs(&out[base + (size_t)r * 128], v[r]);   // streaming: never re-read
}

// ---------------------------------------------------------------------------
extern "C" void kernel_launch(void* const* d_in, const int* in_sizes, int n_in,
                              void* d_out, int out_size) {
    const float* inp = (const float*)d_in[0];
    const float* wk  = (const float*)d_in[1];
    if (n_in >= 2 && in_sizes[0] == 48) {  // defensive: swap if order flipped
        inp = (const float*)d_in[1];
        wk  = (const float*)d_in[0];
    }

    gate_conv_kernel<<<4096, 256>>>((const float4*)inp, wk);
    gate_select_kernel<<<64, 512>>>();
    // 128 cols x 64 row-pairs = 8192 threads per (c,b); /256 = 32 blocks
    dim3 mgrid(32, 3, 64);
    gate_mul_kernel<<<mgrid, 256>>>((const float4*)inp, (float4*)d_out);
}